// round 1
// baseline (speedup 1.0000x reference)
#include <cuda_runtime.h>
#include <cstdint>
#include <cstdio>

#define NN 100000
#define NE 600000
#define HH 128

// ---------------- static device buffers (allocation-free scratch) ----------
__device__ __align__(16) float g_h   [(size_t)NN*HH];
__device__ __align__(16) float g_agg0[(size_t)NN*HH];
__device__ __align__(16) float g_agg1[(size_t)NN*HH];
__device__ __align__(16) float g_hr  [(size_t)NN*HH];
__device__ __align__(16) float g_hh2 [(size_t)NN*HH];
__device__ __align__(16) float g_hp  [(size_t)NN*HH];
__device__ __align__(16) float g_v   [(size_t)NN*HH];
__device__ __align__(16) float g_att [(size_t)NN*HH];
__device__ __align__(16) float g_hq  [(size_t)NN*HH];
__device__ __align__(16) float g_gi  [(size_t)NN*3*HH];
__device__ __align__(16) float g_gh  [(size_t)NN*3*HH];
__device__ __align__(16) float g_f   [(size_t)NN*64];
__device__ unsigned      g_ntbits[NN];
__device__ int           g_degtot[NN];
__device__ int           g_degrec[NN];
__device__ unsigned char g_upd[NN];
__device__ unsigned      g_hist0[2048];
__device__ unsigned      g_histB[2*2048];
__device__ unsigned      g_histC[2*1024];
__device__ unsigned      g_prefix[2];
__device__ unsigned      g_krem[2];
__device__ float         g_med;
__device__ unsigned      g_ntmin_u, g_ntmax_u;
__device__ float         g_bvo[HH];

__device__ __forceinline__ float wredsum(float v){
    #pragma unroll
    for (int o=16;o;o>>=1) v += __shfl_xor_sync(0xffffffffu, v, o);
    return v;
}

// ---------------- init: zero all per-call state ----------------------------
__global__ void k_init(){
    size_t idx = (size_t)blockIdx.x*blockDim.x + threadIdx.x;
    size_t str = (size_t)gridDim.x*blockDim.x;
    for (size_t i=idx; i<(size_t)NN*HH; i+=str){ g_agg0[i]=0.f; g_agg1[i]=0.f; }
    for (size_t i=idx; i<NN; i+=str){ g_ntbits[i]=0u; g_degtot[i]=0; g_degrec[i]=0; g_upd[i]=0; }
    for (size_t i=idx; i<2048; i+=str) g_hist0[i]=0u;
    if (idx==0){ g_ntmin_u=0xFFFFFFFFu; g_ntmax_u=0u; }
}

// ---------------- edge pass 1: scatter-max nt, upd flags, deg_tot, hist0 ---
__global__ void k_edge1(const int* __restrict__ row, const int* __restrict__ col,
                        const float* __restrict__ ts){
    __shared__ unsigned sh[2048];
    for (int i=threadIdx.x;i<2048;i+=blockDim.x) sh[i]=0u;
    __syncthreads();
    int idx = blockIdx.x*blockDim.x + threadIdx.x;
    int str = gridDim.x*blockDim.x;
    for (int e=idx; e<NE; e+=str){
        float t = ts[e];
        unsigned key = __float_as_uint(t);           // ts >= 0 -> uint order == float order
        atomicAdd(&sh[key>>21], 1u);
        int r = row[e], c = col[e];
        g_upd[r]=1; g_upd[c]=1;
        atomicMax(&g_ntbits[c], key);
        atomicAdd(&g_degtot[c], 1);
    }
    __syncthreads();
    for (int i=threadIdx.x;i<2048;i+=blockDim.x)
        if (sh[i]) atomicAdd(&g_hist0[i], sh[i]);
}

// ---------------- exact median via 3-pass radix select (ranks 299999,300000)
__global__ void k_scan0(){
    __shared__ unsigned sh[2048];
    __shared__ unsigned cum[2049];
    int t = threadIdx.x;
    for (int i=t;i<2048;i+=blockDim.x) sh[i]=g_hist0[i];
    __syncthreads();
    if (t==0){ unsigned run=0; for (int i=0;i<2048;i++){ cum[i]=run; run+=sh[i]; } cum[2048]=run; }
    __syncthreads();
    for (int i=t;i<2048;i+=blockDim.x){
        #pragma unroll
        for (int s=0;s<2;s++){
            unsigned k = 299999u + (unsigned)s;
            if (k>=cum[i] && k<cum[i+1]){ g_prefix[s]=(unsigned)i; g_krem[s]=k-cum[i]; }
        }
    }
    for (int i=t;i<4096;i+=blockDim.x) g_histB[i]=0u;
}

__global__ void k_hist1(const float* __restrict__ ts){
    int e = blockIdx.x*blockDim.x + threadIdx.x;
    if (e>=NE) return;
    unsigned p0 = g_prefix[0], p1 = g_prefix[1];
    unsigned key = __float_as_uint(ts[e]);
    unsigned hi = key>>21;
    unsigned bin = (key>>10)&0x7FFu;
    if (hi==p0) atomicAdd(&g_histB[bin], 1u);
    if (hi==p1) atomicAdd(&g_histB[2048+bin], 1u);
}

__global__ void k_scan1(){
    __shared__ unsigned sh[2048];
    __shared__ unsigned cum[2049];
    __shared__ unsigned skrem, spfx;
    int t = threadIdx.x;
    for (int s=0;s<2;s++){
        for (int i=t;i<2048;i+=blockDim.x) sh[i]=g_histB[s*2048+i];
        __syncthreads();
        if (t==0){
            unsigned run=0; for (int i=0;i<2048;i++){ cum[i]=run; run+=sh[i]; } cum[2048]=run;
            skrem = g_krem[s]; spfx = g_prefix[s];
        }
        __syncthreads();
        unsigned k = skrem, pf = spfx;
        for (int i=t;i<2048;i+=blockDim.x)
            if (k>=cum[i] && k<cum[i+1]){ g_prefix[s]=(pf<<11)|(unsigned)i; g_krem[s]=k-cum[i]; }
        __syncthreads();
    }
    for (int i=t;i<2048;i+=blockDim.x) g_histC[i]=0u;
}

__global__ void k_hist2(const float* __restrict__ ts){
    int e = blockIdx.x*blockDim.x + threadIdx.x;
    if (e>=NE) return;
    unsigned p0 = g_prefix[0], p1 = g_prefix[1];
    unsigned key = __float_as_uint(ts[e]);
    unsigned hi = key>>10;
    unsigned bin = key&1023u;
    if (hi==p0) atomicAdd(&g_histC[bin], 1u);
    if (hi==p1) atomicAdd(&g_histC[1024+bin], 1u);
}

__global__ void k_scan2(){
    __shared__ unsigned sh[1024];
    __shared__ unsigned cum[1025];
    __shared__ unsigned skrem, spfx;
    __shared__ float vals[2];
    int t = threadIdx.x;
    for (int s=0;s<2;s++){
        for (int i=t;i<1024;i+=blockDim.x) sh[i]=g_histC[s*1024+i];
        __syncthreads();
        if (t==0){
            unsigned run=0; for (int i=0;i<1024;i++){ cum[i]=run; run+=sh[i]; } cum[1024]=run;
            skrem = g_krem[s]; spfx = g_prefix[s];
        }
        __syncthreads();
        unsigned k = skrem, pf = spfx;
        for (int i=t;i<1024;i+=blockDim.x)
            if (k>=cum[i] && k<cum[i+1]) vals[s] = __uint_as_float((pf<<10)|(unsigned)i);
        __syncthreads();
    }
    if (t==0) g_med = 0.5f*(vals[0]+vals[1]);
}

// ---------------- nt min/max reduction --------------------------------------
__global__ void k_ntmm(){
    int i = blockIdx.x*blockDim.x + threadIdx.x;
    unsigned mn = 0xFFFFFFFFu, mx = 0u;
    if (i<NN){ unsigned v = g_ntbits[i]; mn=v; mx=v; }
    #pragma unroll
    for (int o=16;o;o>>=1){
        unsigned a = __shfl_xor_sync(0xffffffffu, mn, o); mn = (a<mn)?a:mn;
        unsigned b = __shfl_xor_sync(0xffffffffu, mx, o); mx = (b>mx)?b:mx;
    }
    if ((threadIdx.x&31)==0){
        atomicMin(&g_ntmin_u, mn);
        atomicMax(&g_ntmax_u, mx);
    }
}

// ---------------- generic tiled GEMM: C[M,N] = A[M,K] * B[N,K]^T ------------
__global__ __launch_bounds__(256) void k_gemm(const float* __restrict__ A,
                                              const float* __restrict__ B,
                                              float* __restrict__ C,
                                              int M, int N, int K){
    __shared__ float As[32][68];
    __shared__ float Bs[32][68];
    int bm = blockIdx.y*64, bn = blockIdx.x*64;
    int t = threadIdx.x;
    int tm = (t>>4)<<2, tn = (t&15)<<2;
    float acc[4][4] = {};
    for (int k0=0; k0<K; k0+=32){
        #pragma unroll
        for (int i=0;i<8;i++){
            int l = t + i*256;
            int m = l>>5, k = l&31;
            int gk = k0+k;
            float va = 0.f, vb = 0.f;
            int gm = bm+m, gn = bn+m;
            if (gm<M && gk<K) va = A[(size_t)gm*K + gk];
            if (gn<N && gk<K) vb = B[(size_t)gn*K + gk];
            As[k][m] = va;
            Bs[k][m] = vb;
        }
        __syncthreads();
        #pragma unroll
        for (int k=0;k<32;k++){
            float a[4], b[4];
            *(float4*)a = *(const float4*)&As[k][tm];
            *(float4*)b = *(const float4*)&Bs[k][tn];
            #pragma unroll
            for (int i=0;i<4;i++)
                #pragma unroll
                for (int j=0;j<4;j++)
                    acc[i][j] += a[i]*b[j];
        }
        __syncthreads();
    }
    #pragma unroll
    for (int i=0;i<4;i++){
        int gm = bm+tm+i;
        if (gm>=M) break;
        if (bn+tn+3 < N){
            *(float4*)&C[(size_t)gm*N + bn+tn] = make_float4(acc[i][0],acc[i][1],acc[i][2],acc[i][3]);
        } else {
            #pragma unroll
            for (int j=0;j<4;j++) if (bn+tn+j<N) C[(size_t)gm*N + bn+tn+j] = acc[i][j];
        }
    }
}

// ---------------- E1: h = relu(h0 + b_in + ntn*wt + bt) + memory ------------
__global__ void k_e1(const float* __restrict__ b_in, const float* __restrict__ wt,
                     const float* __restrict__ bt, const float* __restrict__ mem){
    size_t idx = (size_t)blockIdx.x*blockDim.x + threadIdx.x;
    if (idx >= (size_t)NN*HH) return;
    int i = (int)(idx>>7), j = (int)(idx&127);
    float tmin = __uint_as_float(g_ntmin_u);
    float tmax = __uint_as_float(g_ntmax_u);
    float nt = __uint_as_float(g_ntbits[i]);
    float ntn = (tmax>tmin) ? (nt-tmin)/(tmax-tmin+1e-8f) : nt;
    float h = g_h[idx] + b_in[j] + ntn*wt[j] + bt[j];
    h = fmaxf(h, 0.f) + mem[idx];
    g_h[idx] = h;
}

// ---------------- E2: GRU gate combine -> new_memory -------------------------
__global__ void k_e2(const float* __restrict__ b_ih, const float* __restrict__ b_hh,
                     const float* __restrict__ mem, float* __restrict__ out_nm){
    size_t idx = (size_t)blockIdx.x*blockDim.x + threadIdx.x;
    if (idx >= (size_t)NN*HH) return;
    int i = (int)(idx>>7), j = (int)(idx&127);
    size_t base = (size_t)i*384;
    float ir = g_gi[base+j]     + b_ih[j];
    float iz = g_gi[base+128+j] + b_ih[128+j];
    float ic = g_gi[base+256+j] + b_ih[256+j];
    float hr = g_gh[base+j]     + b_hh[j];
    float hz = g_gh[base+128+j] + b_hh[128+j];
    float hc = g_gh[base+256+j] + b_hh[256+j];
    float r = 1.f/(1.f+expf(-(ir+hr)));
    float z = 1.f/(1.f+expf(-(iz+hz)));
    float c = tanhf(ic + r*hc);
    float m = mem[idx];
    out_nm[idx] = g_upd[i] ? ((1.f-z)*c + z*m) : m;
}

// ---------------- deg_rec pass ----------------------------------------------
__global__ void k_deg(const int* __restrict__ col, const float* __restrict__ ts){
    int e = blockIdx.x*blockDim.x + threadIdx.x;
    if (e>=NE) return;
    if (ts[e] >= g_med) atomicAdd(&g_degrec[col[e]], 1);
}

// ---------------- edge scatter: agg_p[col] += coef * h[row] ------------------
__global__ void k_scatter(const int* __restrict__ row, const int* __restrict__ col,
                          const float* __restrict__ ts){
    int gw = (blockIdx.x*blockDim.x + threadIdx.x)>>5;
    if (gw>=NE) return;
    int lane = threadIdx.x&31;
    int r = row[gw], c = col[gw];
    float t = ts[gw];
    float med = g_med;
    int rec = (t >= med);
    int drr = g_degrec[r], drc = g_degrec[c];
    float dr = (float)((rec ? drr : g_degtot[r]-drr) + 1);
    float dc = (float)((rec ? drc : g_degtot[c]-drc) + 1);
    float coef = rsqrtf(dr)*rsqrtf(dc);
    float4 hv = *(const float4*)&g_h[(size_t)r*HH + lane*4];
    float* dst = (rec ? g_agg0 : g_agg1) + (size_t)c*HH + lane*4;
    asm volatile("red.global.add.v4.f32 [%0], {%1,%2,%3,%4};"
                 :: "l"(dst), "f"(hv.x*coef), "f"(hv.y*coef), "f"(hv.z*coef), "f"(hv.w*coef)
                 : "memory");
}

// ---------------- E3: fold self-loop term into agg ---------------------------
__global__ void k_e3(){
    size_t idx = (size_t)blockIdx.x*blockDim.x + threadIdx.x;
    if (idx >= (size_t)NN*HH) return;
    int i = (int)(idx>>7);
    int drec = g_degrec[i], dtot = g_degtot[i];
    float hv = g_h[idx];
    g_agg0[idx] += hv * (1.f/(float)(drec+1));
    g_agg1[idx] += hv * (1.f/(float)(dtot-drec+1));
}

// ---------------- E4: multi-path softmax combine + LayerNorm -----------------
__global__ void k_e4(const float* __restrict__ b_gr, const float* __restrict__ b_gh,
                     const float* __restrict__ lg, const float* __restrict__ lb){
    int w = (blockIdx.x*blockDim.x + threadIdx.x)>>5;
    if (w>=NN) return;
    int lane = threadIdx.x&31;
    size_t base = (size_t)w*HH;
    float hr[4], hh[4];
    float s0=0.f, s1=0.f;
    #pragma unroll
    for (int q=0;q<4;q++){
        int j = lane + 32*q;
        hr[q] = g_hr[base+j]  + b_gr[j];
        hh[q] = g_hh2[base+j] + b_gh[j];
        s0 += hr[q]; s1 += hh[q];
    }
    s0 = wredsum(s0); s1 = wredsum(s1);
    float m0 = s0*(1.f/128.f), m1 = s1*(1.f/128.f);
    float mx = fmaxf(m0,m1);
    float e0 = expf(m0-mx), e1 = expf(m1-mx);
    float inv = 1.f/(e0+e1);
    float w0 = e0*inv, w1 = e1*inv;
    float c[4]; float s=0.f;
    #pragma unroll
    for (int q=0;q<4;q++){ c[q] = w0*hr[q] + w1*hh[q]; s += c[q]; }
    s = wredsum(s);
    float mu = s*(1.f/128.f);
    float vs=0.f;
    #pragma unroll
    for (int q=0;q<4;q++){ float d=c[q]-mu; vs += d*d; }
    vs = wredsum(vs);
    float istd = rsqrtf(vs*(1.f/128.f) + 1e-5f);
    #pragma unroll
    for (int q=0;q<4;q++){
        int j = lane + 32*q;
        g_hp[base+j] = (c[q]-mu)*istd*lg[j] + lb[j];
    }
}

// ---------------- bvo = Wo @ bv + bo -----------------------------------------
__global__ void k_bvo(const float* __restrict__ bv, const float* __restrict__ Wo,
                      const float* __restrict__ bo){
    int j = threadIdx.x;
    float a = bo[j];
    for (int k=0;k<HH;k++) a += bv[k]*Wo[j*HH+k];
    g_bvo[j] = a;
}

// ---------------- E6: hq = LN(hp + att + bvo) --------------------------------
__global__ void k_e6(const float* __restrict__ lg, const float* __restrict__ lb){
    int w = (blockIdx.x*blockDim.x + threadIdx.x)>>5;
    if (w>=NN) return;
    int lane = threadIdx.x&31;
    size_t base = (size_t)w*HH;
    float c[4]; float s=0.f;
    #pragma unroll
    for (int q=0;q<4;q++){
        int j = lane + 32*q;
        c[q] = g_hp[base+j] + g_att[base+j] + g_bvo[j];
        s += c[q];
    }
    s = wredsum(s);
    float mu = s*(1.f/128.f);
    float vs=0.f;
    #pragma unroll
    for (int q=0;q<4;q++){ float d=c[q]-mu; vs += d*d; }
    vs = wredsum(vs);
    float istd = rsqrtf(vs*(1.f/128.f) + 1e-5f);
    #pragma unroll
    for (int q=0;q<4;q++){
        int j = lane + 32*q;
        g_hq[base+j] = (c[q]-mu)*istd*lg[j] + lb[j];
    }
}

// ---------------- final: logits = relu(f+b1) @ W2^T + b2 ---------------------
__global__ void k_final(const float* __restrict__ b1, const float* __restrict__ W2,
                        const float* __restrict__ b2, float* __restrict__ out){
    int w = (blockIdx.x*blockDim.x + threadIdx.x)>>5;
    if (w>=NN) return;
    int lane = threadIdx.x&31;
    float f0 = fmaxf(g_f[(size_t)w*64 + lane]      + b1[lane],    0.f);
    float f1 = fmaxf(g_f[(size_t)w*64 + 32 + lane] + b1[32+lane], 0.f);
    float l0 = f0*W2[lane]    + f1*W2[32+lane];
    float l1 = f0*W2[64+lane] + f1*W2[96+lane];
    l0 = wredsum(l0); l1 = wredsum(l1);
    if (lane==0){
        out[(size_t)w*2]   = l0 + b2[0];
        out[(size_t)w*2+1] = l1 + b2[1];
    }
}

// ---------------- host driver -------------------------------------------------
static float* symf(const void* s){ void* p=nullptr; cudaGetSymbolAddress(&p, s); return (float*)p; }

extern "C" void kernel_launch(void* const* d_in, const int* in_sizes, int n_in,
                              void* d_out, int out_size){
    const float* x      = (const float*)d_in[0];
    const int*   ei     = (const int*)  d_in[1];
    const float* ts     = (const float*)d_in[2];
    const float* mem    = (const float*)d_in[3];
    const float* W_in   = (const float*)d_in[4];
    const float* b_in   = (const float*)d_in[5];
    const float* W_time = (const float*)d_in[6];
    const float* b_time = (const float*)d_in[7];
    const float* W_ih   = (const float*)d_in[8];
    const float* W_hh   = (const float*)d_in[9];
    const float* b_ih   = (const float*)d_in[10];
    const float* b_hh   = (const float*)d_in[11];
    const float* W_gr   = (const float*)d_in[12];
    const float* b_gr   = (const float*)d_in[13];
    const float* W_gh   = (const float*)d_in[14];
    const float* b_gh   = (const float*)d_in[15];
    const float* ln_pa_g= (const float*)d_in[16];
    const float* ln_pa_b= (const float*)d_in[17];
    const float* Wv     = (const float*)d_in[18];
    const float* bv     = (const float*)d_in[19];
    const float* Wo     = (const float*)d_in[20];
    const float* bo     = (const float*)d_in[21];
    const float* ln_at_g= (const float*)d_in[22];
    const float* ln_at_b= (const float*)d_in[23];
    const float* W1     = (const float*)d_in[24];
    const float* b1     = (const float*)d_in[25];
    const float* W2     = (const float*)d_in[26];
    const float* b2     = (const float*)d_in[27];
    const int* row = ei;
    const int* col = ei + NE;

    float* out        = (float*)d_out;
    float* out_logits = out;           // [N,2]
    float* out_newmem = out + 2*(size_t)NN;  // [N,128]

    float* p_h    = symf(g_h);
    float* p_agg0 = symf(g_agg0);
    float* p_agg1 = symf(g_agg1);
    float* p_hr   = symf(g_hr);
    float* p_hh2  = symf(g_hh2);
    float* p_hp   = symf(g_hp);
    float* p_v    = symf(g_v);
    float* p_att  = symf(g_att);
    float* p_hq   = symf(g_hq);
    float* p_gi   = symf(g_gi);
    float* p_gh   = symf(g_gh);
    float* p_f    = symf(g_f);

    const int EB = (NE+255)/256;            // edge blocks
    const int EWB = (NE*32+255)/256;        // warp-per-edge blocks
    const int NHB = (int)(((size_t)NN*HH+255)/256);
    const int NWB = (NN*32+255)/256;        // warp-per-node blocks
    const int MY = (NN+63)/64;

    k_init<<<1024,256>>>();
    k_edge1<<<264,256>>>(row,col,ts);
    k_scan0<<<1,256>>>();
    k_hist1<<<EB,256>>>(ts);
    k_scan1<<<1,256>>>();
    k_hist2<<<EB,256>>>(ts);
    k_scan2<<<1,256>>>();
    k_ntmm<<<(NN+255)/256,256>>>();

    // h = relu(x@W_in^T + b_in + ntn*wt + bt) + memory
    k_gemm<<<dim3(2,MY),256>>>(x, W_in, p_h, NN, 128, 166);
    k_e1<<<NHB,256>>>(b_in, W_time, b_time, mem);

    // GRU
    k_gemm<<<dim3(6,MY),256>>>(p_h,  W_ih, p_gi, NN, 384, 128);
    k_gemm<<<dim3(6,MY),256>>>(mem,  W_hh, p_gh, NN, 384, 128);
    k_e2<<<NHB,256>>>(b_ih, b_hh, mem, out_newmem);

    // GCN paths: deg, scatter raw h, fold self loops, then linear
    k_deg<<<EB,256>>>(col, ts);
    k_scatter<<<EWB,256>>>(row, col, ts);
    k_e3<<<NHB,256>>>();
    k_gemm<<<dim3(2,MY),256>>>(p_agg0, W_gr, p_hr,  NN, 128, 128);
    k_gemm<<<dim3(2,MY),256>>>(p_agg1, W_gh, p_hh2, NN, 128, 128);
    k_e4<<<NWB,256>>>(b_gr, b_gh, ln_pa_g, ln_pa_b);

    // attention (query path cancels): att = (hp@Wv^T)@Wo^T, biases folded via bvo
    k_bvo<<<1,128>>>(bv, Wo, bo);
    k_gemm<<<dim3(2,MY),256>>>(p_hp, Wv, p_v,   NN, 128, 128);
    k_gemm<<<dim3(2,MY),256>>>(p_v,  Wo, p_att, NN, 128, 128);
    k_e6<<<NWB,256>>>(ln_at_g, ln_at_b);

    // classifier
    k_gemm<<<dim3(1,MY),256>>>(p_hq, W1, p_f, NN, 64, 128);
    k_final<<<NWB,256>>>(b1, W2, b2, out_logits);

    (void)in_sizes; (void)n_in; (void)out_size;
}

// round 4
// speedup vs baseline: 1.5162x; 1.5162x over previous
#include <cuda_runtime.h>
#include <cstdint>
#include <cstdio>

#define NN 100000
#define NE 600000
#define HH 128

// ---------------- static device buffers (allocation-free scratch) ----------
__device__ __align__(16) float g_h   [(size_t)NN*HH];
__device__ __align__(16) float g_agg0[(size_t)NN*HH];
__device__ __align__(16) float g_agg1[(size_t)NN*HH];
__device__ __align__(16) float g_hr  [(size_t)NN*HH];
__device__ __align__(16) float g_hh2 [(size_t)NN*HH];
__device__ __align__(16) float g_hp  [(size_t)NN*HH];
__device__ __align__(16) float g_att [(size_t)NN*HH];
__device__ __align__(16) float g_hq  [(size_t)NN*HH];
__device__ __align__(16) float g_gi  [(size_t)NN*3*HH];
__device__ __align__(16) float g_gh  [(size_t)NN*3*HH];
__device__ __align__(16) float g_f   [(size_t)NN*64];
__device__ __align__(16) float g_wf  [HH*HH];     // Wo @ Wv
__device__ float         g_s0[NN];                 // self-loop scale recent
__device__ float         g_s1[NN];                 // self-loop scale history
__device__ unsigned      g_ntbits[NN];
__device__ int           g_degtot[NN];
__device__ int           g_degrec[NN];
__device__ unsigned char g_upd[NN];
__device__ unsigned      g_hist0[2048];
__device__ unsigned      g_histB[2*2048];
__device__ unsigned      g_histC[2*1024];
__device__ unsigned      g_prefix[2];
__device__ unsigned      g_krem[2];
__device__ float         g_med;
__device__ unsigned      g_ntmin_u, g_ntmax_u;
__device__ float         g_bvo[HH];

__device__ __forceinline__ float wredsum(float v){
    #pragma unroll
    for (int o=16;o;o>>=1) v += __shfl_xor_sync(0xffffffffu, v, o);
    return v;
}

__device__ __forceinline__ unsigned long long pk2(float lo, float hi){
    unsigned long long r;
    asm("mov.b64 %0,{%1,%2};" : "=l"(r) : "f"(lo), "f"(hi));
    return r;
}
__device__ __forceinline__ void upk2(unsigned long long v, float& lo, float& hi){
    asm("mov.b64 {%0,%1},%2;" : "=f"(lo), "=f"(hi) : "l"(v));
}
#define FMA2(d,a,b) asm("fma.rn.f32x2 %0,%1,%2,%0;" : "+l"(d) : "l"(a), "l"(b))

// ---------------- init: zero all per-call state ----------------------------
__global__ void k_init(){
    size_t idx = (size_t)blockIdx.x*blockDim.x + threadIdx.x;
    size_t str = (size_t)gridDim.x*blockDim.x;
    for (size_t i=idx; i<(size_t)NN*HH; i+=str){ g_agg0[i]=0.f; g_agg1[i]=0.f; }
    for (size_t i=idx; i<NN; i+=str){ g_ntbits[i]=0u; g_degtot[i]=0; g_degrec[i]=0; g_upd[i]=0; }
    for (size_t i=idx; i<2048; i+=str) g_hist0[i]=0u;
    if (idx==0){ g_ntmin_u=0xFFFFFFFFu; g_ntmax_u=0u; }
}

// ---------------- edge pass 1: scatter-max nt, upd flags, deg_tot, hist0 ---
__global__ void k_edge1(const int* __restrict__ row, const int* __restrict__ col,
                        const float* __restrict__ ts){
    __shared__ unsigned sh[2048];
    for (int i=threadIdx.x;i<2048;i+=blockDim.x) sh[i]=0u;
    __syncthreads();
    int idx = blockIdx.x*blockDim.x + threadIdx.x;
    int str = gridDim.x*blockDim.x;
    for (int e=idx; e<NE; e+=str){
        float t = ts[e];
        unsigned key = __float_as_uint(t);           // ts >= 0 -> uint order == float order
        atomicAdd(&sh[key>>21], 1u);
        int r = row[e], c = col[e];
        g_upd[r]=1; g_upd[c]=1;
        atomicMax(&g_ntbits[c], key);
        atomicAdd(&g_degtot[c], 1);
    }
    __syncthreads();
    for (int i=threadIdx.x;i<2048;i+=blockDim.x)
        if (sh[i]) atomicAdd(&g_hist0[i], sh[i]);
}

// ---------------- exact median via 3-pass radix select (ranks 299999,300000)
__global__ void k_scan0(){
    __shared__ unsigned sh[2048];
    __shared__ unsigned cum[2049];
    int t = threadIdx.x;
    for (int i=t;i<2048;i+=blockDim.x) sh[i]=g_hist0[i];
    __syncthreads();
    if (t==0){ unsigned run=0; for (int i=0;i<2048;i++){ cum[i]=run; run+=sh[i]; } cum[2048]=run; }
    __syncthreads();
    for (int i=t;i<2048;i+=blockDim.x){
        #pragma unroll
        for (int s=0;s<2;s++){
            unsigned k = 299999u + (unsigned)s;
            if (k>=cum[i] && k<cum[i+1]){ g_prefix[s]=(unsigned)i; g_krem[s]=k-cum[i]; }
        }
    }
    for (int i=t;i<4096;i+=blockDim.x) g_histB[i]=0u;
}

__global__ void k_hist1(const float* __restrict__ ts){
    int e = blockIdx.x*blockDim.x + threadIdx.x;
    if (e>=NE) return;
    unsigned p0 = g_prefix[0], p1 = g_prefix[1];
    unsigned key = __float_as_uint(ts[e]);
    unsigned hi = key>>21;
    unsigned bin = (key>>10)&0x7FFu;
    if (hi==p0) atomicAdd(&g_histB[bin], 1u);
    if (hi==p1) atomicAdd(&g_histB[2048+bin], 1u);
}

__global__ void k_scan1(){
    __shared__ unsigned sh[2048];
    __shared__ unsigned cum[2049];
    __shared__ unsigned skrem, spfx;
    int t = threadIdx.x;
    for (int s=0;s<2;s++){
        for (int i=t;i<2048;i+=blockDim.x) sh[i]=g_histB[s*2048+i];
        __syncthreads();
        if (t==0){
            unsigned run=0; for (int i=0;i<2048;i++){ cum[i]=run; run+=sh[i]; } cum[2048]=run;
            skrem = g_krem[s]; spfx = g_prefix[s];
        }
        __syncthreads();
        unsigned k = skrem, pf = spfx;
        for (int i=t;i<2048;i+=blockDim.x)
            if (k>=cum[i] && k<cum[i+1]){ g_prefix[s]=(pf<<11)|(unsigned)i; g_krem[s]=k-cum[i]; }
        __syncthreads();
    }
    for (int i=t;i<2048;i+=blockDim.x) g_histC[i]=0u;
}

__global__ void k_hist2(const float* __restrict__ ts){
    int e = blockIdx.x*blockDim.x + threadIdx.x;
    if (e>=NE) return;
    unsigned p0 = g_prefix[0], p1 = g_prefix[1];
    unsigned key = __float_as_uint(ts[e]);
    unsigned hi = key>>10;
    unsigned bin = key&1023u;
    if (hi==p0) atomicAdd(&g_histC[bin], 1u);
    if (hi==p1) atomicAdd(&g_histC[1024+bin], 1u);
}

__global__ void k_scan2(){
    __shared__ unsigned sh[1024];
    __shared__ unsigned cum[1025];
    __shared__ unsigned skrem, spfx;
    __shared__ float vals[2];
    int t = threadIdx.x;
    for (int s=0;s<2;s++){
        for (int i=t;i<1024;i+=blockDim.x) sh[i]=g_histC[s*1024+i];
        __syncthreads();
        if (t==0){
            unsigned run=0; for (int i=0;i<1024;i++){ cum[i]=run; run+=sh[i]; } cum[1024]=run;
            skrem = g_krem[s]; spfx = g_prefix[s];
        }
        __syncthreads();
        unsigned k = skrem, pf = spfx;
        for (int i=t;i<1024;i+=blockDim.x)
            if (k>=cum[i] && k<cum[i+1]) vals[s] = __uint_as_float((pf<<10)|(unsigned)i);
        __syncthreads();
    }
    if (t==0) g_med = 0.5f*(vals[0]+vals[1]);
}

// ---------------- nt min/max reduction --------------------------------------
__global__ void k_ntmm(){
    int i = blockIdx.x*blockDim.x + threadIdx.x;
    unsigned mn = 0xFFFFFFFFu, mx = 0u;
    if (i<NN){ unsigned v = g_ntbits[i]; mn=v; mx=v; }
    #pragma unroll
    for (int o=16;o;o>>=1){
        unsigned a = __shfl_xor_sync(0xffffffffu, mn, o); mn = (a<mn)?a:mn;
        unsigned b = __shfl_xor_sync(0xffffffffu, mx, o); mx = (b>mx)?b:mx;
    }
    if ((threadIdx.x&31)==0){
        atomicMin(&g_ntmin_u, mn);
        atomicMax(&g_ntmax_u, mx);
    }
}

// ---------------- FFMA2 GEMM: C[M,N] = (A + rs.*A2)[M,K] * B[N,K]^T ---------
// 128x128 block tile, 256 threads, 8x8 per thread, double-buffered smem.
__global__ __launch_bounds__(256,2) void k_gemm2(const float* __restrict__ A,
        const float* __restrict__ A2, const float* __restrict__ rs,
        const float* __restrict__ B, float* __restrict__ C,
        int M, int N, int K)
{
    __shared__ float As[2][16][132];
    __shared__ float Bs[2][16][132];
    const int t = threadIdx.x;
    const int tx = t & 15, ty = t >> 4;
    const int bm = blockIdx.y * 128, bn = blockIdx.x * 128;
    unsigned long long acc[8][4];
    #pragma unroll
    for (int i=0;i<8;i++)
        #pragma unroll
        for (int j=0;j<4;j++) acc[i][j]=0ull;

    const int nk = (K + 15) >> 4;

#define COMPUTE(cur)                                                          \
    _Pragma("unroll")                                                         \
    for (int kk=0;kk<16;kk++){                                                \
        float4 a0 = *(const float4*)&As[cur][kk][ty*8];                       \
        float4 a1 = *(const float4*)&As[cur][kk][ty*8+4];                     \
        float4 b0 = *(const float4*)&Bs[cur][kk][tx*8];                       \
        float4 b1 = *(const float4*)&Bs[cur][kk][tx*8+4];                     \
        unsigned long long bp0=pk2(b0.x,b0.y), bp1=pk2(b0.z,b0.w);            \
        unsigned long long bp2=pk2(b1.x,b1.y), bp3=pk2(b1.z,b1.w);            \
        float av[8]={a0.x,a0.y,a0.z,a0.w,a1.x,a1.y,a1.z,a1.w};                \
        _Pragma("unroll")                                                     \
        for (int i=0;i<8;i++){                                                \
            unsigned long long ap = pk2(av[i],av[i]);                         \
            FMA2(acc[i][0],ap,bp0); FMA2(acc[i][1],ap,bp1);                   \
            FMA2(acc[i][2],ap,bp2); FMA2(acc[i][3],ap,bp3);                   \
        }                                                                     \
    }

    if ((K & 15) == 0){
        float4 ra[2], rb[2];
#define LDGV(k0)                                                              \
        _Pragma("unroll")                                                     \
        for (int i=0;i<2;i++){                                                \
            int idx = t + i*256;                                              \
            int m = idx>>2, kq = (idx&3)<<2;                                  \
            int gm = bm+m, gn = bn+m, gk = (k0)+kq;                           \
            float4 va = {0.f,0.f,0.f,0.f}, vb = {0.f,0.f,0.f,0.f};            \
            if (gm<M){ va = *(const float4*)&A[(size_t)gm*K+gk];              \
                if (A2){ float4 w = *(const float4*)&A2[(size_t)gm*K+gk];     \
                    float s = rs[gm];                                         \
                    va.x += s*w.x; va.y += s*w.y; va.z += s*w.z; va.w += s*w.w; } } \
            if (gn<N) vb = *(const float4*)&B[(size_t)gn*K+gk];               \
            ra[i]=va; rb[i]=vb;                                               \
        }
#define STSV(s)                                                               \
        _Pragma("unroll")                                                     \
        for (int i=0;i<2;i++){                                                \
            int idx = t + i*256;                                              \
            int m = idx>>2, kq = (idx&3)<<2;                                  \
            As[s][kq+0][m]=ra[i].x; As[s][kq+1][m]=ra[i].y;                   \
            As[s][kq+2][m]=ra[i].z; As[s][kq+3][m]=ra[i].w;                   \
            Bs[s][kq+0][m]=rb[i].x; Bs[s][kq+1][m]=rb[i].y;                   \
            Bs[s][kq+2][m]=rb[i].z; Bs[s][kq+3][m]=rb[i].w;                   \
        }
        LDGV(0);
        STSV(0);
        __syncthreads();
        for (int c=0;c<nk;c++){
            int cur = c & 1;
            if (c+1<nk){ LDGV((c+1)*16); }
            COMPUTE(cur);
            if (c+1<nk){ STSV((c+1)&1); }
            __syncthreads();
        }
    } else {
        float sa[8], sb[8];
#define LDGS(k0)                                                              \
        _Pragma("unroll")                                                     \
        for (int i=0;i<8;i++){                                                \
            int lin = t + i*256;                                              \
            int k = lin & 15, m = lin >> 4;                                   \
            int gm = bm+m, gn = bn+m, gk = (k0)+k;                            \
            float va = 0.f, vb = 0.f;                                         \
            if (gm<M && gk<K){ va = A[(size_t)gm*K+gk];                       \
                if (A2) va += rs[gm]*A2[(size_t)gm*K+gk]; }                   \
            if (gn<N && gk<K) vb = B[(size_t)gn*K+gk];                        \
            sa[i]=va; sb[i]=vb;                                               \
        }
#define STSS(s)                                                               \
        _Pragma("unroll")                                                     \
        for (int i=0;i<8;i++){                                                \
            int lin = t + i*256;                                              \
            int k = lin & 15, m = lin >> 4;                                   \
            As[s][k][m]=sa[i]; Bs[s][k][m]=sb[i];                             \
        }
        LDGS(0);
        STSS(0);
        __syncthreads();
        for (int c=0;c<nk;c++){
            int cur = c & 1;
            if (c+1<nk){ LDGS((c+1)*16); }
            COMPUTE(cur);
            if (c+1<nk){ STSS((c+1)&1); }
            __syncthreads();
        }
    }

    // store
    #pragma unroll
    for (int i=0;i<8;i++){
        int gm = bm + ty*8 + i;
        if (gm >= M) break;
        float o[8];
        upk2(acc[i][0], o[0], o[1]);
        upk2(acc[i][1], o[2], o[3]);
        upk2(acc[i][2], o[4], o[5]);
        upk2(acc[i][3], o[6], o[7]);
        int gn = bn + tx*8;
        if (gn + 7 < N){
            *(float4*)&C[(size_t)gm*N + gn]     = make_float4(o[0],o[1],o[2],o[3]);
            *(float4*)&C[(size_t)gm*N + gn + 4] = make_float4(o[4],o[5],o[6],o[7]);
        } else {
            #pragma unroll
            for (int j=0;j<8;j++) if (gn+j < N) C[(size_t)gm*N + gn + j] = o[j];
        }
    }
#undef COMPUTE
#undef LDGV
#undef STSV
#undef LDGS
#undef STSS
}

// ---------------- E1: h = relu(h0 + b_in + ntn*wt + bt) + memory ------------
__global__ void k_e1(const float* __restrict__ b_in, const float* __restrict__ wt,
                     const float* __restrict__ bt, const float* __restrict__ mem){
    size_t idx = (size_t)blockIdx.x*blockDim.x + threadIdx.x;
    if (idx >= (size_t)NN*HH) return;
    int i = (int)(idx>>7), j = (int)(idx&127);
    float tmin = __uint_as_float(g_ntmin_u);
    float tmax = __uint_as_float(g_ntmax_u);
    float nt = __uint_as_float(g_ntbits[i]);
    float ntn = (tmax>tmin) ? (nt-tmin)/(tmax-tmin+1e-8f) : nt;
    float h = g_h[idx] + b_in[j] + ntn*wt[j] + bt[j];
    h = fmaxf(h, 0.f) + mem[idx];
    g_h[idx] = h;
}

// ---------------- E2: GRU gate combine -> new_memory -------------------------
__global__ void k_e2(const float* __restrict__ b_ih, const float* __restrict__ b_hh,
                     const float* __restrict__ mem, float* __restrict__ out_nm){
    size_t idx = (size_t)blockIdx.x*blockDim.x + threadIdx.x;
    if (idx >= (size_t)NN*HH) return;
    int i = (int)(idx>>7), j = (int)(idx&127);
    size_t base = (size_t)i*384;
    float ir = g_gi[base+j]     + b_ih[j];
    float iz = g_gi[base+128+j] + b_ih[128+j];
    float ic = g_gi[base+256+j] + b_ih[256+j];
    float hr = g_gh[base+j]     + b_hh[j];
    float hz = g_gh[base+128+j] + b_hh[128+j];
    float hc = g_gh[base+256+j] + b_hh[256+j];
    float r = 1.f/(1.f+expf(-(ir+hr)));
    float z = 1.f/(1.f+expf(-(iz+hz)));
    float c = tanhf(ic + r*hc);
    float m = mem[idx];
    out_nm[idx] = g_upd[i] ? ((1.f-z)*c + z*m) : m;
}

// ---------------- deg_rec pass ----------------------------------------------
__global__ void k_deg(const int* __restrict__ col, const float* __restrict__ ts){
    int e = blockIdx.x*blockDim.x + threadIdx.x;
    if (e>=NE) return;
    if (ts[e] >= g_med) atomicAdd(&g_degrec[col[e]], 1);
}

// ---------------- self-loop row scales ---------------------------------------
__global__ void k_sscale(){
    int i = blockIdx.x*blockDim.x + threadIdx.x;
    if (i>=NN) return;
    int drec = g_degrec[i], dtot = g_degtot[i];
    g_s0[i] = 1.f/(float)(drec+1);
    g_s1[i] = 1.f/(float)(dtot-drec+1);
}

// ---------------- edge scatter: agg_p[col] += coef * h[row] ------------------
__global__ void k_scatter(const int* __restrict__ row, const int* __restrict__ col,
                          const float* __restrict__ ts){
    int gw = (blockIdx.x*blockDim.x + threadIdx.x)>>5;
    if (gw>=NE) return;
    int lane = threadIdx.x&31;
    int r = row[gw], c = col[gw];
    float t = ts[gw];
    float med = g_med;
    int rec = (t >= med);
    int drr = g_degrec[r], drc = g_degrec[c];
    float dr = (float)((rec ? drr : g_degtot[r]-drr) + 1);
    float dc = (float)((rec ? drc : g_degtot[c]-drc) + 1);
    float coef = rsqrtf(dr)*rsqrtf(dc);
    float4 hv = *(const float4*)&g_h[(size_t)r*HH + lane*4];
    float* dst = (rec ? g_agg0 : g_agg1) + (size_t)c*HH + lane*4;
    asm volatile("red.global.add.v4.f32 [%0], {%1,%2,%3,%4};"
                 :: "l"(dst), "f"(hv.x*coef), "f"(hv.y*coef), "f"(hv.z*coef), "f"(hv.w*coef)
                 : "memory");
}

// ---------------- E4: multi-path softmax combine + LayerNorm -----------------
__global__ void k_e4(const float* __restrict__ b_gr, const float* __restrict__ b_gh,
                     const float* __restrict__ lg, const float* __restrict__ lb){
    int w = (blockIdx.x*blockDim.x + threadIdx.x)>>5;
    if (w>=NN) return;
    int lane = threadIdx.x&31;
    size_t base = (size_t)w*HH;
    float hr[4], hh[4];
    float s0=0.f, s1=0.f;
    #pragma unroll
    for (int q=0;q<4;q++){
        int j = lane + 32*q;
        hr[q] = g_hr[base+j]  + b_gr[j];
        hh[q] = g_hh2[base+j] + b_gh[j];
        s0 += hr[q]; s1 += hh[q];
    }
    s0 = wredsum(s0); s1 = wredsum(s1);
    float m0 = s0*(1.f/128.f), m1 = s1*(1.f/128.f);
    float mx = fmaxf(m0,m1);
    float e0 = expf(m0-mx), e1 = expf(m1-mx);
    float inv = 1.f/(e0+e1);
    float w0 = e0*inv, w1 = e1*inv;
    float c[4]; float s=0.f;
    #pragma unroll
    for (int q=0;q<4;q++){ c[q] = w0*hr[q] + w1*hh[q]; s += c[q]; }
    s = wredsum(s);
    float mu = s*(1.f/128.f);
    float vs=0.f;
    #pragma unroll
    for (int q=0;q<4;q++){ float d=c[q]-mu; vs += d*d; }
    vs = wredsum(vs);
    float istd = rsqrtf(vs*(1.f/128.f) + 1e-5f);
    #pragma unroll
    for (int q=0;q<4;q++){
        int j = lane + 32*q;
        g_hp[base+j] = (c[q]-mu)*istd*lg[j] + lb[j];
    }
}

// ---------------- bvo = Wo @ bv + bo -----------------------------------------
__global__ void k_bvo(const float* __restrict__ bv, const float* __restrict__ Wo,
                      const float* __restrict__ bo){
    int j = threadIdx.x;
    float a = bo[j];
    for (int k=0;k<HH;k++) a += bv[k]*Wo[j*HH+k];
    g_bvo[j] = a;
}

// ---------------- Wf = Wo @ Wv (so att = hp @ Wf^T + bvo) --------------------
__global__ void k_wf(const float* __restrict__ Wo, const float* __restrict__ Wv){
    __shared__ float srow[HH];
    int i = blockIdx.x;           // output row
    int k = threadIdx.x;          // output col
    srow[k] = Wo[i*HH + k];
    __syncthreads();
    float a = 0.f;
    #pragma unroll 8
    for (int j=0;j<HH;j++) a += srow[j]*Wv[j*HH + k];
    g_wf[i*HH + k] = a;
}

// ---------------- E6: hq = LN(hp + att + bvo) --------------------------------
__global__ void k_e6(const float* __restrict__ lg, const float* __restrict__ lb){
    int w = (blockIdx.x*blockDim.x + threadIdx.x)>>5;
    if (w>=NN) return;
    int lane = threadIdx.x&31;
    size_t base = (size_t)w*HH;
    float c[4]; float s=0.f;
    #pragma unroll
    for (int q=0;q<4;q++){
        int j = lane + 32*q;
        c[q] = g_hp[base+j] + g_att[base+j] + g_bvo[j];
        s += c[q];
    }
    s = wredsum(s);
    float mu = s*(1.f/128.f);
    float vs=0.f;
    #pragma unroll
    for (int q=0;q<4;q++){ float d=c[q]-mu; vs += d*d; }
    vs = wredsum(vs);
    float istd = rsqrtf(vs*(1.f/128.f) + 1e-5f);
    #pragma unroll
    for (int q=0;q<4;q++){
        int j = lane + 32*q;
        g_hq[base+j] = (c[q]-mu)*istd*lg[j] + lb[j];
    }
}

// ---------------- final: logits = relu(f+b1) @ W2^T + b2 ---------------------
__global__ void k_final(const float* __restrict__ b1, const float* __restrict__ W2,
                        const float* __restrict__ b2, float* __restrict__ out){
    int w = (blockIdx.x*blockDim.x + threadIdx.x)>>5;
    if (w>=NN) return;
    int lane = threadIdx.x&31;
    float f0 = fmaxf(g_f[(size_t)w*64 + lane]      + b1[lane],    0.f);
    float f1 = fmaxf(g_f[(size_t)w*64 + 32 + lane] + b1[32+lane], 0.f);
    float l0 = f0*W2[lane]    + f1*W2[32+lane];
    float l1 = f0*W2[64+lane] + f1*W2[96+lane];
    l0 = wredsum(l0); l1 = wredsum(l1);
    if (lane==0){
        out[(size_t)w*2]   = l0 + b2[0];
        out[(size_t)w*2+1] = l1 + b2[1];
    }
}

// ---------------- host driver -------------------------------------------------
static float* symf(const void* s){ void* p=nullptr; cudaGetSymbolAddress(&p, s); return (float*)p; }

extern "C" void kernel_launch(void* const* d_in, const int* in_sizes, int n_in,
                              void* d_out, int out_size){
    const float* x      = (const float*)d_in[0];
    const int*   ei     = (const int*)  d_in[1];
    const float* ts     = (const float*)d_in[2];
    const float* mem    = (const float*)d_in[3];
    const float* W_in   = (const float*)d_in[4];
    const float* b_in   = (const float*)d_in[5];
    const float* W_time = (const float*)d_in[6];
    const float* b_time = (const float*)d_in[7];
    const float* W_ih   = (const float*)d_in[8];
    const float* W_hh   = (const float*)d_in[9];
    const float* b_ih   = (const float*)d_in[10];
    const float* b_hh   = (const float*)d_in[11];
    const float* W_gr   = (const float*)d_in[12];
    const float* b_gr   = (const float*)d_in[13];
    const float* W_gh   = (const float*)d_in[14];
    const float* b_gh   = (const float*)d_in[15];
    const float* ln_pa_g= (const float*)d_in[16];
    const float* ln_pa_b= (const float*)d_in[17];
    const float* Wv     = (const float*)d_in[18];
    const float* bv     = (const float*)d_in[19];
    const float* Wo     = (const float*)d_in[20];
    const float* bo     = (const float*)d_in[21];
    const float* ln_at_g= (const float*)d_in[22];
    const float* ln_at_b= (const float*)d_in[23];
    const float* W1     = (const float*)d_in[24];
    const float* b1     = (const float*)d_in[25];
    const float* W2     = (const float*)d_in[26];
    const float* b2     = (const float*)d_in[27];
    const int* row = ei;
    const int* col = ei + NE;

    float* out        = (float*)d_out;
    float* out_logits = out;                 // [N,2]
    float* out_newmem = out + 2*(size_t)NN;  // [N,128]

    float* p_h    = symf(g_h);
    float* p_agg0 = symf(g_agg0);
    float* p_agg1 = symf(g_agg1);
    float* p_hr   = symf(g_hr);
    float* p_hh2  = symf(g_hh2);
    float* p_hp   = symf(g_hp);
    float* p_att  = symf(g_att);
    float* p_hq   = symf(g_hq);
    float* p_gi   = symf(g_gi);
    float* p_gh   = symf(g_gh);
    float* p_f    = symf(g_f);
    float* p_wf   = symf(g_wf);
    float* p_s0   = symf(g_s0);
    float* p_s1   = symf(g_s1);

    const int EB  = (NE+255)/256;             // edge blocks
    const int EWB = (NE*32+255)/256;          // warp-per-edge blocks
    const int NHB = (int)(((size_t)NN*HH+255)/256);
    const int NWB = (NN*32+255)/256;          // warp-per-node blocks
    const int MY  = (NN+127)/128;             // GEMM m-tiles

    k_init<<<1024,256>>>();
    k_wf<<<HH,HH>>>(Wo, Wv);
    k_bvo<<<1,128>>>(bv, Wo, bo);
    k_edge1<<<264,256>>>(row,col,ts);
    k_scan0<<<1,256>>>();
    k_hist1<<<EB,256>>>(ts);
    k_scan1<<<1,256>>>();
    k_hist2<<<EB,256>>>(ts);
    k_scan2<<<1,256>>>();
    k_ntmm<<<(NN+255)/256,256>>>();

    // h = relu(x@W_in^T + b_in + ntn*wt + bt) + memory
    k_gemm2<<<dim3(1,MY),256>>>(x, nullptr, nullptr, W_in, p_h, NN, 128, 166);
    k_e1<<<NHB,256>>>(b_in, W_time, b_time, mem);

    // GRU
    k_gemm2<<<dim3(3,MY),256>>>(p_h,  nullptr, nullptr, W_ih, p_gi, NN, 384, 128);
    k_gemm2<<<dim3(3,MY),256>>>(mem,  nullptr, nullptr, W_hh, p_gh, NN, 384, 128);
    k_e2<<<NHB,256>>>(b_ih, b_hh, mem, out_newmem);

    // GCN paths: deg, scatter raw h, linear with fused self-loop fold
    k_deg<<<EB,256>>>(col, ts);
    k_sscale<<<(NN+255)/256,256>>>();
    k_scatter<<<EWB,256>>>(row, col, ts);
    k_gemm2<<<dim3(1,MY),256>>>(p_agg0, p_h, p_s0, W_gr, p_hr,  NN, 128, 128);
    k_gemm2<<<dim3(1,MY),256>>>(p_agg1, p_h, p_s1, W_gh, p_hh2, NN, 128, 128);
    k_e4<<<NWB,256>>>(b_gr, b_gh, ln_pa_g, ln_pa_b);

    // attention (query path cancels; Wv/Wo fused): att = hp @ (Wo Wv)^T, biases via bvo
    k_gemm2<<<dim3(1,MY),256>>>(p_hp, nullptr, nullptr, p_wf, p_att, NN, 128, 128);
    k_e6<<<NWB,256>>>(ln_at_g, ln_at_b);

    // classifier
    k_gemm2<<<dim3(1,MY),256>>>(p_hq, nullptr, nullptr, W1, p_f, NN, 64, 128);
    k_final<<<NWB,256>>>(b1, W2, b2, out_logits);

    (void)in_sizes; (void)n_in; (void)out_size;
}

// round 13
// speedup vs baseline: 2.1913x; 1.4453x over previous
#include <cuda_runtime.h>
#include <cstdint>
#include <cstdio>

#define NN 100000
#define NE 600000
#define HH 128

// ---------------- static device buffers (allocation-free scratch) ----------
__device__ __align__(16) float g_h   [(size_t)NN*HH];
__device__ __align__(16) float g_agg0[(size_t)NN*HH];
__device__ __align__(16) float g_agg1[(size_t)NN*HH];
__device__ __align__(16) float g_hr  [(size_t)NN*HH];
__device__ __align__(16) float g_hh2 [(size_t)NN*HH];
__device__ __align__(16) float g_hp  [(size_t)NN*HH];
__device__ __align__(16) float g_att [(size_t)NN*HH];
__device__ __align__(16) float g_hq  [(size_t)NN*HH];
__device__ __align__(16) float g_gi  [(size_t)NN*3*HH];
__device__ __align__(16) float g_gh  [(size_t)NN*3*HH];
__device__ __align__(16) float g_f   [(size_t)NN*64];
__device__ __align__(16) float g_wf  [HH*HH];     // Wo @ Wv
__device__ float         g_s0[NN];
__device__ float         g_s1[NN];
__device__ unsigned      g_ntbits[NN];
__device__ int           g_degtot[NN];
__device__ int           g_degrec[NN];
__device__ unsigned char g_upd[NN];
__device__ unsigned      g_hist0[2048];
__device__ unsigned      g_histB[2*2048];
__device__ unsigned      g_histC[2*1024];
__device__ unsigned      g_prefix[2];
__device__ unsigned      g_krem[2];
__device__ float         g_med;
__device__ unsigned      g_ntmin_u, g_ntmax_u;
__device__ float         g_bvo[HH];

__device__ __forceinline__ float wredsum(float v){
    #pragma unroll
    for (int o=16;o;o>>=1) v += __shfl_xor_sync(0xffffffffu, v, o);
    return v;
}
__device__ __forceinline__ uint32_t smem_u32(const void* p){
    uint32_t a;
    asm("{ .reg .u64 t; cvta.to.shared.u64 t, %1; cvt.u32.u64 %0, t; }" : "=r"(a) : "l"(p));
    return a;
}
__device__ __forceinline__ uint32_t bf2(float e0, float e1){   // mem order: e0,e1
    uint32_t r;
    asm("cvt.rn.bf16x2.f32 %0, %2, %1;" : "=r"(r) : "f"(e0), "f"(e1));
    return r;
}
__device__ __forceinline__ uint32_t hipack(float a, float b){  // trunc-bf16 pair (a,b)
    uint32_t r;
    asm("prmt.b32 %0,%1,%2,0x7632;" : "=r"(r) : "r"(__float_as_uint(a)), "r"(__float_as_uint(b)));
    return r;
}
__device__ __forceinline__ float lopart(float v){
    return v - __uint_as_float(__float_as_uint(v) & 0xffff0000u);
}

#define LDSM4(d0,d1,d2,d3,addr) \
    asm volatile("ldmatrix.sync.aligned.m8n8.x4.shared.b16 {%0,%1,%2,%3}, [%4];" \
        : "=r"(d0),"=r"(d1),"=r"(d2),"=r"(d3) : "r"(addr))

#define MMA(c,a0,a1,a2,a3,b0,b1) \
    asm volatile("mma.sync.aligned.m16n8k16.row.col.f32.bf16.bf16.f32 " \
        "{%0,%1,%2,%3},{%4,%5,%6,%7},{%8,%9},{%0,%1,%2,%3};" \
        : "+f"((c)[0]),"+f"((c)[1]),"+f"((c)[2]),"+f"((c)[3]) \
        : "r"(a0),"r"(a1),"r"(a2),"r"(a3),"r"(b0),"r"(b1))

// ---------------- init: zero all per-call state ----------------------------
__global__ void k_init(){
    size_t idx = (size_t)blockIdx.x*blockDim.x + threadIdx.x;
    size_t str = (size_t)gridDim.x*blockDim.x;
    for (size_t i=idx; i<(size_t)NN*HH; i+=str){ g_agg0[i]=0.f; g_agg1[i]=0.f; }
    for (size_t i=idx; i<NN; i+=str){ g_ntbits[i]=0u; g_degtot[i]=0; g_degrec[i]=0; g_upd[i]=0; }
    for (size_t i=idx; i<2048; i+=str) g_hist0[i]=0u;
    if (idx==0){ g_ntmin_u=0xFFFFFFFFu; g_ntmax_u=0u; }
}

// ---------------- HMMA bf16 3-split GEMM: C[M,N] = (A + rs.*A2)[M,K] * B[N,K]^T
// 128x128 block tile, 256 threads (8 warps, 4x2), warp tile 32x64.
// Per 16-k chunk: fp32 -> hi/lo bf16 tiles in smem (stride 24 bf16 = 48B),
// accumulate hi*hi + lo*hi + hi*lo in fp32 via mma.sync m16n8k16.
// Vector (float4) global loads only when K % 4 == 0 (else misaligned rows).
__global__ __launch_bounds__(256,2) void k_mma(const float* __restrict__ A,
        const float* __restrict__ A2, const float* __restrict__ rs,
        const float* __restrict__ B, float* __restrict__ C,
        int M, int N, int K)
{
    __shared__ __align__(16) uint16_t sAh[128*24], sAl[128*24], sBh[128*24], sBl[128*24];
    const int tid = threadIdx.x, lane = tid&31, wid = tid>>5;
    const int bm = blockIdx.y*128, bn = blockIdx.x*128;
    const int row = tid>>1, half = tid&1;
    const int gm = bm + row;           // A source row for staging
    const int gn = bn + row;           // B source row for staging
    const bool kv4 = ((K & 3) == 0);   // float4-safe rows

    float acc[2][8][4];
    #pragma unroll
    for (int i=0;i<2;i++)
        #pragma unroll
        for (int j=0;j<8;j++)
            #pragma unroll
            for (int q=0;q<4;q++) acc[i][j][q]=0.f;

    const int nch = (K+15)>>4;
    float a_st[8], b_st[8];

#define LOADC(c) do{                                                          \
        int gk0 = (c)*16 + half*8;                                            \
        if (gm < M){                                                          \
            if (kv4 && gk0+8 <= K){                                           \
                float4 v0 = *(const float4*)&A[(size_t)gm*K+gk0];             \
                float4 v1 = *(const float4*)&A[(size_t)gm*K+gk0+4];           \
                if (A2){                                                      \
                    float s = rs[gm];                                         \
                    float4 w0 = *(const float4*)&A2[(size_t)gm*K+gk0];        \
                    float4 w1 = *(const float4*)&A2[(size_t)gm*K+gk0+4];      \
                    v0.x+=s*w0.x; v0.y+=s*w0.y; v0.z+=s*w0.z; v0.w+=s*w0.w;   \
                    v1.x+=s*w1.x; v1.y+=s*w1.y; v1.z+=s*w1.z; v1.w+=s*w1.w;   \
                }                                                             \
                a_st[0]=v0.x; a_st[1]=v0.y; a_st[2]=v0.z; a_st[3]=v0.w;       \
                a_st[4]=v1.x; a_st[5]=v1.y; a_st[6]=v1.z; a_st[7]=v1.w;       \
            } else {                                                          \
                float s = A2 ? rs[gm] : 0.f;                                  \
                _Pragma("unroll")                                             \
                for (int e=0;e<8;e++){                                        \
                    int gk = gk0+e;                                           \
                    float v = 0.f;                                            \
                    if (gk < K){                                              \
                        v = A[(size_t)gm*K+gk];                               \
                        if (A2) v += s*A2[(size_t)gm*K+gk];                   \
                    }                                                         \
                    a_st[e] = v;                                              \
                }                                                             \
            }                                                                 \
        } else {                                                              \
            _Pragma("unroll") for (int e=0;e<8;e++) a_st[e]=0.f;              \
        }                                                                     \
        if (gn < N){                                                          \
            if (kv4 && gk0+8 <= K){                                           \
                float4 v0 = *(const float4*)&B[(size_t)gn*K+gk0];             \
                float4 v1 = *(const float4*)&B[(size_t)gn*K+gk0+4];           \
                b_st[0]=v0.x; b_st[1]=v0.y; b_st[2]=v0.z; b_st[3]=v0.w;       \
                b_st[4]=v1.x; b_st[5]=v1.y; b_st[6]=v1.z; b_st[7]=v1.w;       \
            } else {                                                          \
                _Pragma("unroll")                                             \
                for (int e=0;e<8;e++){                                        \
                    int gk = gk0+e;                                           \
                    b_st[e] = (gk < K) ? B[(size_t)gn*K+gk] : 0.f;            \
                }                                                             \
            }                                                                 \
        } else {                                                              \
            _Pragma("unroll") for (int e=0;e<8;e++) b_st[e]=0.f;              \
        }                                                                     \
    } while(0)

#define STOREC() do{                                                          \
        uint32_t ha[4], la[4], hb[4], lb[4];                                  \
        _Pragma("unroll")                                                     \
        for (int q=0;q<4;q++){                                                \
            ha[q] = hipack(a_st[2*q], a_st[2*q+1]);                           \
            la[q] = bf2(lopart(a_st[2*q]), lopart(a_st[2*q+1]));              \
            hb[q] = hipack(b_st[2*q], b_st[2*q+1]);                           \
            lb[q] = bf2(lopart(b_st[2*q]), lopart(b_st[2*q+1]));              \
        }                                                                     \
        int so = row*24 + half*8;                                             \
        *(uint4*)&sAh[so] = make_uint4(ha[0],ha[1],ha[2],ha[3]);              \
        *(uint4*)&sAl[so] = make_uint4(la[0],la[1],la[2],la[3]);              \
        *(uint4*)&sBh[so] = make_uint4(hb[0],hb[1],hb[2],hb[3]);              \
        *(uint4*)&sBl[so] = make_uint4(lb[0],lb[1],lb[2],lb[3]);              \
    } while(0)

    const int wm = (wid>>1)*32, wn = (wid&1)*64;
    const int r8 = lane&7, grp = lane>>3;
    const uint32_t bAh = smem_u32(sAh), bAl = smem_u32(sAl);
    const uint32_t bBh = smem_u32(sBh), bBl = smem_u32(sBl);
    // A frag addr: mats (mlo,klo),(mhi,klo),(mlo,khi),(mhi,khi)
    const uint32_t offA0 = (uint32_t)(((wm +      r8 + ((grp&1)<<3))*24 + ((grp>>1)<<3))*2);
    const uint32_t offA1 = offA0 + 16u*24u*2u;
    // B frag addr: mats (nlo,klo),(nlo,khi),(nhi,klo),(nhi,khi)
    const uint32_t offB  = (uint32_t)(((wn + r8 + (((grp>>1)&1)<<3))*24 + ((grp&1)<<3))*2);

    LOADC(0);
    for (int c=0;c<nch;c++){
        STOREC();
        __syncthreads();
        if (c+1<nch){ LOADC(c+1); }
        // compute from smem
        uint32_t aH[2][4], aL[2][4];
        LDSM4(aH[0][0],aH[0][1],aH[0][2],aH[0][3], bAh + offA0);
        LDSM4(aH[1][0],aH[1][1],aH[1][2],aH[1][3], bAh + offA1);
        LDSM4(aL[0][0],aL[0][1],aL[0][2],aL[0][3], bAl + offA0);
        LDSM4(aL[1][0],aL[1][1],aL[1][2],aL[1][3], bAl + offA1);
        #pragma unroll
        for (int jt=0;jt<4;jt++){
            uint32_t bH[4], bL[4];
            uint32_t ob = offB + (uint32_t)(jt*16*24*2);
            LDSM4(bH[0],bH[1],bH[2],bH[3], bBh + ob);
            LDSM4(bL[0],bL[1],bL[2],bL[3], bBl + ob);
            #pragma unroll
            for (int i=0;i<2;i++){
                #pragma unroll
                for (int jj=0;jj<2;jj++){
                    float* cc = acc[i][jt*2+jj];
                    MMA(cc, aH[i][0],aH[i][1],aH[i][2],aH[i][3], bH[jj*2],bH[jj*2+1]);
                    MMA(cc, aL[i][0],aL[i][1],aL[i][2],aL[i][3], bH[jj*2],bH[jj*2+1]);
                    MMA(cc, aH[i][0],aH[i][1],aH[i][2],aH[i][3], bL[jj*2],bL[jj*2+1]);
                }
            }
        }
        __syncthreads();
    }

    // epilogue: direct global stores from c-frags
    const int cr = lane>>2, ccol = (lane&3)*2;
    #pragma unroll
    for (int i=0;i<2;i++){
        #pragma unroll
        for (int j=0;j<8;j++){
            int gmm = bm + wm + i*16 + cr;
            int gnn = bn + wn + j*8 + ccol;
            float* cc = acc[i][j];
            if (gnn < N){
                if (gmm < M)   *(float2*)&C[(size_t)gmm*N+gnn]     = make_float2(cc[0],cc[1]);
                if (gmm+8 < M) *(float2*)&C[(size_t)(gmm+8)*N+gnn] = make_float2(cc[2],cc[3]);
            }
        }
    }
#undef LOADC
#undef STOREC
}

// ---------------- edge pass: upd flags, scatter-max nt, deg_tot --------------
__global__ void k_edge1a(const int* __restrict__ row, const int* __restrict__ col,
                         const float* __restrict__ ts){
    int e = blockIdx.x*blockDim.x + threadIdx.x;
    if (e>=NE) return;
    unsigned key = __float_as_uint(ts[e]);   // ts >= 0 -> uint order == float order
    int r = row[e], c = col[e];
    g_upd[r]=1; g_upd[c]=1;
    atomicMax(&g_ntbits[c], key);
    atomicAdd(&g_degtot[c], 1);
}

// ---------------- hist pass 0 -------------------------------------------------
__global__ void k_hist0(const float* __restrict__ ts){
    __shared__ unsigned sh[2048];
    for (int i=threadIdx.x;i<2048;i+=blockDim.x) sh[i]=0u;
    __syncthreads();
    int idx = blockIdx.x*blockDim.x + threadIdx.x;
    int str = gridDim.x*blockDim.x;
    for (int e=idx; e<NE; e+=str){
        unsigned key = __float_as_uint(ts[e]);
        atomicAdd(&sh[key>>21], 1u);
    }
    __syncthreads();
    for (int i=threadIdx.x;i<2048;i+=blockDim.x)
        if (sh[i]) atomicAdd(&g_hist0[i], sh[i]);
}

// ---------------- exact median via 3-pass radix select (ranks 299999,300000)
__global__ void k_scan0(){
    __shared__ unsigned sh[2048];
    __shared__ unsigned cum[2049];
    int t = threadIdx.x;
    for (int i=t;i<2048;i+=blockDim.x) sh[i]=g_hist0[i];
    __syncthreads();
    if (t==0){ unsigned run=0; for (int i=0;i<2048;i++){ cum[i]=run; run+=sh[i]; } cum[2048]=run; }
    __syncthreads();
    for (int i=t;i<2048;i+=blockDim.x){
        #pragma unroll
        for (int s=0;s<2;s++){
            unsigned k = 299999u + (unsigned)s;
            if (k>=cum[i] && k<cum[i+1]){ g_prefix[s]=(unsigned)i; g_krem[s]=k-cum[i]; }
        }
    }
    for (int i=t;i<4096;i+=blockDim.x) g_histB[i]=0u;
}

__global__ void k_hist1(const float* __restrict__ ts){
    int e = blockIdx.x*blockDim.x + threadIdx.x;
    if (e>=NE) return;
    unsigned p0 = g_prefix[0], p1 = g_prefix[1];
    unsigned key = __float_as_uint(ts[e]);
    unsigned hi = key>>21;
    unsigned bin = (key>>10)&0x7FFu;
    if (hi==p0) atomicAdd(&g_histB[bin], 1u);
    if (hi==p1) atomicAdd(&g_histB[2048+bin], 1u);
}

__global__ void k_scan1(){
    __shared__ unsigned sh[2048];
    __shared__ unsigned cum[2049];
    __shared__ unsigned skrem, spfx;
    int t = threadIdx.x;
    for (int s=0;s<2;s++){
        for (int i=t;i<2048;i+=blockDim.x) sh[i]=g_histB[s*2048+i];
        __syncthreads();
        if (t==0){
            unsigned run=0; for (int i=0;i<2048;i++){ cum[i]=run; run+=sh[i]; } cum[2048]=run;
            skrem = g_krem[s]; spfx = g_prefix[s];
        }
        __syncthreads();
        unsigned k = skrem, pf = spfx;
        for (int i=t;i<2048;i+=blockDim.x)
            if (k>=cum[i] && k<cum[i+1]){ g_prefix[s]=(pf<<11)|(unsigned)i; g_krem[s]=k-cum[i]; }
        __syncthreads();
    }
    for (int i=t;i<2048;i+=blockDim.x) g_histC[i]=0u;
}

__global__ void k_hist2(const float* __restrict__ ts){
    int e = blockIdx.x*blockDim.x + threadIdx.x;
    if (e>=NE) return;
    unsigned p0 = g_prefix[0], p1 = g_prefix[1];
    unsigned key = __float_as_uint(ts[e]);
    unsigned hi = key>>10;
    unsigned bin = key&1023u;
    if (hi==p0) atomicAdd(&g_histC[bin], 1u);
    if (hi==p1) atomicAdd(&g_histC[1024+bin], 1u);
}

__global__ void k_scan2(){
    __shared__ unsigned sh[1024];
    __shared__ unsigned cum[1025];
    __shared__ unsigned skrem, spfx;
    __shared__ float vals[2];
    int t = threadIdx.x;
    for (int s=0;s<2;s++){
        for (int i=t;i<1024;i+=blockDim.x) sh[i]=g_histC[s*1024+i];
        __syncthreads();
        if (t==0){
            unsigned run=0; for (int i=0;i<1024;i++){ cum[i]=run; run+=sh[i]; } cum[1024]=run;
            skrem = g_krem[s]; spfx = g_prefix[s];
        }
        __syncthreads();
        unsigned k = skrem, pf = spfx;
        for (int i=t;i<1024;i+=blockDim.x)
            if (k>=cum[i] && k<cum[i+1]) vals[s] = __uint_as_float((pf<<10)|(unsigned)i);
        __syncthreads();
    }
    if (t==0) g_med = 0.5f*(vals[0]+vals[1]);
}

// ---------------- nt min/max reduction --------------------------------------
__global__ void k_ntmm(){
    int i = blockIdx.x*blockDim.x + threadIdx.x;
    unsigned mn = 0xFFFFFFFFu, mx = 0u;
    if (i<NN){ unsigned v = g_ntbits[i]; mn=v; mx=v; }
    #pragma unroll
    for (int o=16;o;o>>=1){
        unsigned a = __shfl_xor_sync(0xffffffffu, mn, o); mn = (a<mn)?a:mn;
        unsigned b = __shfl_xor_sync(0xffffffffu, mx, o); mx = (b>mx)?b:mx;
    }
    if ((threadIdx.x&31)==0){
        atomicMin(&g_ntmin_u, mn);
        atomicMax(&g_ntmax_u, mx);
    }
}

// ---------------- E1 ---------------------------------------------------------
__global__ void k_e1(const float* __restrict__ b_in, const float* __restrict__ wt,
                     const float* __restrict__ bt, const float* __restrict__ mem){
    size_t idx = (size_t)blockIdx.x*blockDim.x + threadIdx.x;
    if (idx >= (size_t)NN*HH) return;
    int i = (int)(idx>>7), j = (int)(idx&127);
    float tmin = __uint_as_float(g_ntmin_u);
    float tmax = __uint_as_float(g_ntmax_u);
    float nt = __uint_as_float(g_ntbits[i]);
    float ntn = (tmax>tmin) ? (nt-tmin)/(tmax-tmin+1e-8f) : nt;
    float h = g_h[idx] + b_in[j] + ntn*wt[j] + bt[j];
    h = fmaxf(h, 0.f) + mem[idx];
    g_h[idx] = h;
}

// ---------------- E2: GRU gate combine -> new_memory -------------------------
__global__ void k_e2(const float* __restrict__ b_ih, const float* __restrict__ b_hh,
                     const float* __restrict__ mem, float* __restrict__ out_nm){
    size_t idx = (size_t)blockIdx.x*blockDim.x + threadIdx.x;
    if (idx >= (size_t)NN*HH) return;
    int i = (int)(idx>>7), j = (int)(idx&127);
    size_t base = (size_t)i*384;
    float ir = g_gi[base+j]     + b_ih[j];
    float iz = g_gi[base+128+j] + b_ih[128+j];
    float ic = g_gi[base+256+j] + b_ih[256+j];
    float hr = g_gh[base+j]     + b_hh[j];
    float hz = g_gh[base+128+j] + b_hh[128+j];
    float hc = g_gh[base+256+j] + b_hh[256+j];
    float r = 1.f/(1.f+expf(-(ir+hr)));
    float z = 1.f/(1.f+expf(-(iz+hz)));
    float c = tanhf(ic + r*hc);
    float m = mem[idx];
    out_nm[idx] = g_upd[i] ? ((1.f-z)*c + z*m) : m;
}

// ---------------- deg_rec pass -----------------------------------------------
__global__ void k_deg(const int* __restrict__ col, const float* __restrict__ ts){
    int e = blockIdx.x*blockDim.x + threadIdx.x;
    if (e>=NE) return;
    if (ts[e] >= g_med) atomicAdd(&g_degrec[col[e]], 1);
}

// ---------------- self-loop row scales ----------------------------------------
__global__ void k_sscale(){
    int i = blockIdx.x*blockDim.x + threadIdx.x;
    if (i>=NN) return;
    int drec = g_degrec[i], dtot = g_degtot[i];
    g_s0[i] = 1.f/(float)(drec+1);
    g_s1[i] = 1.f/(float)(dtot-drec+1);
}

// ---------------- edge scatter: agg_p[col] += coef * h[row] -------------------
__global__ void k_scatter(const int* __restrict__ row, const int* __restrict__ col,
                          const float* __restrict__ ts){
    int gw = (blockIdx.x*blockDim.x + threadIdx.x)>>5;
    if (gw>=NE) return;
    int lane = threadIdx.x&31;
    int r = row[gw], c = col[gw];
    float t = ts[gw];
    float med = g_med;
    int rec = (t >= med);
    int drr = g_degrec[r], drc = g_degrec[c];
    float dr = (float)((rec ? drr : g_degtot[r]-drr) + 1);
    float dc = (float)((rec ? drc : g_degtot[c]-drc) + 1);
    float coef = rsqrtf(dr)*rsqrtf(dc);
    float4 hv = *(const float4*)&g_h[(size_t)r*HH + lane*4];
    float* dst = (rec ? g_agg0 : g_agg1) + (size_t)c*HH + lane*4;
    asm volatile("red.global.add.v4.f32 [%0], {%1,%2,%3,%4};"
                 :: "l"(dst), "f"(hv.x*coef), "f"(hv.y*coef), "f"(hv.z*coef), "f"(hv.w*coef)
                 : "memory");
}

// ---------------- E4: multi-path softmax combine + LayerNorm ------------------
__global__ void k_e4(const float* __restrict__ b_gr, const float* __restrict__ b_gh,
                     const float* __restrict__ lg, const float* __restrict__ lb){
    int w = (blockIdx.x*blockDim.x + threadIdx.x)>>5;
    if (w>=NN) return;
    int lane = threadIdx.x&31;
    size_t base = (size_t)w*HH;
    float hr[4], hh[4];
    float s0=0.f, s1=0.f;
    #pragma unroll
    for (int q=0;q<4;q++){
        int j = lane + 32*q;
        hr[q] = g_hr[base+j]  + b_gr[j];
        hh[q] = g_hh2[base+j] + b_gh[j];
        s0 += hr[q]; s1 += hh[q];
    }
    s0 = wredsum(s0); s1 = wredsum(s1);
    float m0 = s0*(1.f/128.f), m1 = s1*(1.f/128.f);
    float mx = fmaxf(m0,m1);
    float e0 = expf(m0-mx), e1 = expf(m1-mx);
    float inv = 1.f/(e0+e1);
    float w0 = e0*inv, w1 = e1*inv;
    float c[4]; float s=0.f;
    #pragma unroll
    for (int q=0;q<4;q++){ c[q] = w0*hr[q] + w1*hh[q]; s += c[q]; }
    s = wredsum(s);
    float mu = s*(1.f/128.f);
    float vs=0.f;
    #pragma unroll
    for (int q=0;q<4;q++){ float d=c[q]-mu; vs += d*d; }
    vs = wredsum(vs);
    float istd = rsqrtf(vs*(1.f/128.f) + 1e-5f);
    #pragma unroll
    for (int q=0;q<4;q++){
        int j = lane + 32*q;
        g_hp[base+j] = (c[q]-mu)*istd*lg[j] + lb[j];
    }
}

// ---------------- bvo = Wo @ bv + bo -------------------------------------------
__global__ void k_bvo(const float* __restrict__ bv, const float* __restrict__ Wo,
                      const float* __restrict__ bo){
    int j = threadIdx.x;
    float a = bo[j];
    for (int k=0;k<HH;k++) a += bv[k]*Wo[j*HH+k];
    g_bvo[j] = a;
}

// ---------------- Wf = Wo @ Wv ---------------------------------------------------
__global__ void k_wf(const float* __restrict__ Wo, const float* __restrict__ Wv){
    __shared__ float srow[HH];
    int i = blockIdx.x;
    int k = threadIdx.x;
    srow[k] = Wo[i*HH + k];
    __syncthreads();
    float a = 0.f;
    #pragma unroll 8
    for (int j=0;j<HH;j++) a += srow[j]*Wv[j*HH + k];
    g_wf[i*HH + k] = a;
}

// ---------------- E6: hq = LN(hp + att + bvo) ------------------------------------
__global__ void k_e6(const float* __restrict__ lg, const float* __restrict__ lb){
    int w = (blockIdx.x*blockDim.x + threadIdx.x)>>5;
    if (w>=NN) return;
    int lane = threadIdx.x&31;
    size_t base = (size_t)w*HH;
    float c[4]; float s=0.f;
    #pragma unroll
    for (int q=0;q<4;q++){
        int j = lane + 32*q;
        c[q] = g_hp[base+j] + g_att[base+j] + g_bvo[j];
        s += c[q];
    }
    s = wredsum(s);
    float mu = s*(1.f/128.f);
    float vs=0.f;
    #pragma unroll
    for (int q=0;q<4;q++){ float d=c[q]-mu; vs += d*d; }
    vs = wredsum(vs);
    float istd = rsqrtf(vs*(1.f/128.f) + 1e-5f);
    #pragma unroll
    for (int q=0;q<4;q++){
        int j = lane + 32*q;
        g_hq[base+j] = (c[q]-mu)*istd*lg[j] + lb[j];
    }
}

// ---------------- final: logits = relu(f+b1) @ W2^T + b2 --------------------------
__global__ void k_final(const float* __restrict__ b1, const float* __restrict__ W2,
                        const float* __restrict__ b2, float* __restrict__ out){
    int w = (blockIdx.x*blockDim.x + threadIdx.x)>>5;
    if (w>=NN) return;
    int lane = threadIdx.x&31;
    float f0 = fmaxf(g_f[(size_t)w*64 + lane]      + b1[lane],    0.f);
    float f1 = fmaxf(g_f[(size_t)w*64 + 32 + lane] + b1[32+lane], 0.f);
    float l0 = f0*W2[lane]    + f1*W2[32+lane];
    float l1 = f0*W2[64+lane] + f1*W2[96+lane];
    l0 = wredsum(l0); l1 = wredsum(l1);
    if (lane==0){
        out[(size_t)w*2]   = l0 + b2[0];
        out[(size_t)w*2+1] = l1 + b2[1];
    }
}

// ---------------- host driver ------------------------------------------------------
static float* symf(const void* s){ void* p=nullptr; cudaGetSymbolAddress(&p, s); return (float*)p; }

extern "C" void kernel_launch(void* const* d_in, const int* in_sizes, int n_in,
                              void* d_out, int out_size){
    const float* x      = (const float*)d_in[0];
    const int*   ei     = (const int*)  d_in[1];
    const float* ts     = (const float*)d_in[2];
    const float* mem    = (const float*)d_in[3];
    const float* W_in   = (const float*)d_in[4];
    const float* b_in   = (const float*)d_in[5];
    const float* W_time = (const float*)d_in[6];
    const float* b_time = (const float*)d_in[7];
    const float* W_ih   = (const float*)d_in[8];
    const float* W_hh   = (const float*)d_in[9];
    const float* b_ih   = (const float*)d_in[10];
    const float* b_hh   = (const float*)d_in[11];
    const float* W_gr   = (const float*)d_in[12];
    const float* b_gr   = (const float*)d_in[13];
    const float* W_gh   = (const float*)d_in[14];
    const float* b_gh   = (const float*)d_in[15];
    const float* ln_pa_g= (const float*)d_in[16];
    const float* ln_pa_b= (const float*)d_in[17];
    const float* Wv     = (const float*)d_in[18];
    const float* bv     = (const float*)d_in[19];
    const float* Wo     = (const float*)d_in[20];
    const float* bo     = (const float*)d_in[21];
    const float* ln_at_g= (const float*)d_in[22];
    const float* ln_at_b= (const float*)d_in[23];
    const float* W1     = (const float*)d_in[24];
    const float* b1     = (const float*)d_in[25];
    const float* W2     = (const float*)d_in[26];
    const float* b2     = (const float*)d_in[27];
    const int* row = ei;
    const int* col = ei + NE;

    float* out        = (float*)d_out;
    float* out_logits = out;                 // [N,2]
    float* out_newmem = out + 2*(size_t)NN;  // [N,128]

    float* p_h    = symf(g_h);
    float* p_agg0 = symf(g_agg0);
    float* p_agg1 = symf(g_agg1);
    float* p_hr   = symf(g_hr);
    float* p_hh2  = symf(g_hh2);
    float* p_hp   = symf(g_hp);
    float* p_att  = symf(g_att);
    float* p_hq   = symf(g_hq);
    float* p_gi   = symf(g_gi);
    float* p_gh   = symf(g_gh);
    float* p_f    = symf(g_f);
    float* p_wf   = symf(g_wf);
    float* p_s0   = symf(g_s0);
    float* p_s1   = symf(g_s1);

    const int EB  = (NE+255)/256;
    const int EWB = (NE*32+255)/256;
    const int NHB = (int)(((size_t)NN*HH+255)/256);
    const int NWB = (NN*32+255)/256;
    const int MY  = (NN+127)/128;

    k_init<<<1024,256>>>();
    k_wf<<<HH,HH>>>(Wo, Wv);
    k_bvo<<<1,128>>>(bv, Wo, bo);

    k_edge1a<<<EB,256>>>(row,col,ts);
    k_hist0<<<264,256>>>(ts);
    k_scan0<<<1,256>>>();
    k_hist1<<<EB,256>>>(ts);
    k_scan1<<<1,256>>>();
    k_hist2<<<EB,256>>>(ts);
    k_scan2<<<1,256>>>();
    k_ntmm<<<(NN+255)/256,256>>>();

    // h = relu(x@W_in^T + ...) + memory
    k_mma<<<dim3(1,MY),256>>>(x, nullptr, nullptr, W_in, p_h, NN, 128, 166);
    k_e1<<<NHB,256>>>(b_in, W_time, b_time, mem);

    // GRU
    k_mma<<<dim3(3,MY),256>>>(p_h,  nullptr, nullptr, W_ih, p_gi, NN, 384, 128);
    k_mma<<<dim3(3,MY),256>>>(mem,  nullptr, nullptr, W_hh, p_gh, NN, 384, 128);
    k_e2<<<NHB,256>>>(b_ih, b_hh, mem, out_newmem);

    // GCN paths
    k_deg<<<EB,256>>>(col, ts);
    k_sscale<<<(NN+255)/256,256>>>();
    k_scatter<<<EWB,256>>>(row, col, ts);
    k_mma<<<dim3(1,MY),256>>>(p_agg0, p_h, p_s0, W_gr, p_hr,  NN, 128, 128);
    k_mma<<<dim3(1,MY),256>>>(p_agg1, p_h, p_s1, W_gh, p_hh2, NN, 128, 128);
    k_e4<<<NWB,256>>>(b_gr, b_gh, ln_pa_g, ln_pa_b);

    // attention (query path cancels; Wv/Wo fused): att = hp @ (Wo Wv)^T
    k_mma<<<dim3(1,MY),256>>>(p_hp, nullptr, nullptr, p_wf, p_att, NN, 128, 128);
    k_e6<<<NWB,256>>>(ln_at_g, ln_at_b);

    // classifier
    k_mma<<<dim3(1,MY),256>>>(p_hq, nullptr, nullptr, W1, p_f, NN, 64, 128);
    k_final<<<NWB,256>>>(b1, W2, b2, out_logits);

    (void)in_sizes; (void)n_in; (void)out_size;
}